// round 2
// baseline (speedup 1.0000x reference)
#include <cuda_runtime.h>
#include <cuda_bf16.h>
#include <math_constants.h>

// Problem constants
#define B_    4
#define N_    2048
#define C_    1024
#define H_    16
#define D_    64
#define BHn   (B_ * H_)          // 64
#define MROWS (B_ * N_)          // 8192

// Scratch (static device arrays; no allocation at runtime)
__device__ float g_q[(size_t)BHn * N_ * D_];     // [bh, n, d], pre-scaled by 1/sqrt(D)
__device__ float g_k[(size_t)BHn * N_ * D_];
__device__ float g_v[(size_t)BHn * N_ * D_];
__device__ float g_ctx[(size_t)MROWS * C_];      // [b, n, h*64+d]

// ---------------------------------------------------------------------------
// Tiled SGEMM: C = A[M,K] @ B[K,N]   (128x128 tile, BK=8, 256 threads, 8x8/thr)
// MODE 0: epilogue scatters into g_q / g_k / g_v (QKV projection, Q scaled)
// MODE 1: A is g_ctx (param ignored), epilogue adds bias, writes Cout
// ---------------------------------------------------------------------------
template <int MODE>
__global__ __launch_bounds__(256) void sgemm_kernel(
    const float* __restrict__ A, const float* __restrict__ Bm,
    const float* __restrict__ bias, float* __restrict__ Cout,
    int M, int Nn, int K)
{
    __shared__ float As[8][128];   // transposed A tile: As[k][m]
    __shared__ float Bs[8][128];   // Bs[k][n]

    const int tid = threadIdx.x;
    const int tx = tid & 15;
    const int ty = tid >> 4;
    const int mBase = blockIdx.y * 128;
    const int nBase = blockIdx.x * 128;

    const int arow = tid >> 1;            // 0..127
    const int ac   = (tid & 1) * 4;       // 0 or 4
    const int brow = tid >> 5;            // 0..7
    const int bc   = (tid & 31) * 4;      // 0..124

    const float* Aptr = (MODE == 1 ? (const float*)g_ctx : A);
    const float* Arow = Aptr + (size_t)(mBase + arow) * K + ac;
    const float* Brow = Bm + (size_t)brow * Nn + nBase + bc;

    float acc[8][8];
#pragma unroll
    for (int i = 0; i < 8; i++)
#pragma unroll
        for (int j = 0; j < 8; j++) acc[i][j] = 0.f;

    for (int k0 = 0; k0 < K; k0 += 8) {
        float4 av = *(const float4*)(Arow + k0);
        float4 bv = *(const float4*)(Brow + (size_t)k0 * Nn);
        __syncthreads();   // previous iteration's smem reads complete
        As[ac + 0][arow] = av.x;
        As[ac + 1][arow] = av.y;
        As[ac + 2][arow] = av.z;
        As[ac + 3][arow] = av.w;
        *(float4*)&Bs[brow][bc] = bv;
        __syncthreads();

#pragma unroll
        for (int kk = 0; kk < 8; kk++) {
            float4 t0 = *(const float4*)&As[kk][ty * 8];
            float4 t1 = *(const float4*)&As[kk][ty * 8 + 4];
            float4 u0 = *(const float4*)&Bs[kk][tx * 8];
            float4 u1 = *(const float4*)&Bs[kk][tx * 8 + 4];
            float a[8] = {t0.x, t0.y, t0.z, t0.w, t1.x, t1.y, t1.z, t1.w};
            float b[8] = {u0.x, u0.y, u0.z, u0.w, u1.x, u1.y, u1.z, u1.w};
#pragma unroll
            for (int i = 0; i < 8; i++)
#pragma unroll
                for (int j = 0; j < 8; j++)
                    acc[i][j] = fmaf(a[i], b[j], acc[i][j]);
        }
    }

    // Epilogue
#pragma unroll
    for (int i = 0; i < 8; i++) {
        const int m = mBase + ty * 8 + i;
#pragma unroll
        for (int j = 0; j < 8; j++) {
            const int n = nBase + tx * 8 + j;
            float v = acc[i][j];
            if (MODE == 0) {
                // n in [0,3072): which = n/1024, h = (n%1024)/64, d = n%64
                const int which = n >> 10;
                const int cc = n & 1023;
                const int h = cc >> 6;
                const int d = cc & 63;
                const int bb = m >> 11;      // m / 2048
                const int nn = m & 2047;
                const size_t off = (((size_t)(bb * H_ + h)) * N_ + nn) * D_ + d;
                if (which == 0)      g_q[off] = v * 0.125f;   // fold 1/sqrt(64)
                else if (which == 1) g_k[off] = v;
                else                 g_v[off] = v;
            } else {
                Cout[(size_t)m * Nn + n] = v + bias[n];
            }
        }
    }
}

// ---------------------------------------------------------------------------
// Flash attention, fp32. One CTA = 64 query rows for one (b,h).
// S tile 64x64, online softmax, O accumulated in registers (4x4 per thread).
// Strided lane mapping (row = ty+16i, col = tx+16j) + stride-65 smem rows
// keeps all LDS conflict-free.
// ---------------------------------------------------------------------------
#define SL 65
#define ATTN_SMEM (3 * 64 * SL * 4)

__global__ __launch_bounds__(256) void attn_kernel()
{
    extern __shared__ float sm[];
    float* Qs  = sm;                 // [64][SL]
    float* KPs = sm + 64 * SL;       // K tile, then reused as P tile
    float* Vs  = sm + 2 * 64 * SL;   // [64][SL]

    const int bh  = blockIdx.y;
    const int q0  = blockIdx.x * 64;
    const int tid = threadIdx.x;
    const int tx  = tid & 15;
    const int ty  = tid >> 4;

    const float* Qg = g_q + (size_t)bh * N_ * D_;
    const float* Kg = g_k + (size_t)bh * N_ * D_;
    const float* Vg = g_v + (size_t)bh * N_ * D_;

    // Load Q tile (64x64)
#pragma unroll
    for (int i = 0; i < 4; i++) {
        const int idx = tid + i * 256;       // float4 units, 1024 total
        const int row = idx >> 4;
        const int c   = (idx & 15) * 4;
        float4 v = *(const float4*)&Qg[(size_t)(q0 + row) * D_ + c];
        Qs[row * SL + c + 0] = v.x;
        Qs[row * SL + c + 1] = v.y;
        Qs[row * SL + c + 2] = v.z;
        Qs[row * SL + c + 3] = v.w;
    }

    float mrow[4], lrow[4], O[4][4];
#pragma unroll
    for (int i = 0; i < 4; i++) {
        mrow[i] = -CUDART_INF_F;
        lrow[i] = 0.f;
#pragma unroll
        for (int j = 0; j < 4; j++) O[i][j] = 0.f;
    }

    for (int kt = 0; kt < N_ / 64; kt++) {
        const int k0 = kt * 64;
        __syncthreads();   // prior iteration done with KPs / Vs
#pragma unroll
        for (int i = 0; i < 4; i++) {
            const int idx = tid + i * 256;
            const int row = idx >> 4;
            const int c   = (idx & 15) * 4;
            float4 kv = *(const float4*)&Kg[(size_t)(k0 + row) * D_ + c];
            KPs[row * SL + c + 0] = kv.x;
            KPs[row * SL + c + 1] = kv.y;
            KPs[row * SL + c + 2] = kv.z;
            KPs[row * SL + c + 3] = kv.w;
            float4 vv = *(const float4*)&Vg[(size_t)(k0 + row) * D_ + c];
            Vs[row * SL + c + 0] = vv.x;
            Vs[row * SL + c + 1] = vv.y;
            Vs[row * SL + c + 2] = vv.z;
            Vs[row * SL + c + 3] = vv.w;
        }
        __syncthreads();

        // S = Q @ K^T (Q pre-scaled)
        float s[4][4];
#pragma unroll
        for (int i = 0; i < 4; i++)
#pragma unroll
            for (int j = 0; j < 4; j++) s[i][j] = 0.f;

        for (int kk = 0; kk < 64; kk++) {
            float a[4], b[4];
#pragma unroll
            for (int i = 0; i < 4; i++) a[i] = Qs[(ty + 16 * i) * SL + kk];
#pragma unroll
            for (int j = 0; j < 4; j++) b[j] = KPs[(tx + 16 * j) * SL + kk];
#pragma unroll
            for (int i = 0; i < 4; i++)
#pragma unroll
                for (int j = 0; j < 4; j++)
                    s[i][j] = fmaf(a[i], b[j], s[i][j]);
        }

        // Online softmax per row (reduce across the 16 tx lanes of each row)
#pragma unroll
        for (int i = 0; i < 4; i++) {
            float mx = fmaxf(fmaxf(s[i][0], s[i][1]), fmaxf(s[i][2], s[i][3]));
            mx = fmaxf(mx, __shfl_xor_sync(0xffffffffu, mx, 1));
            mx = fmaxf(mx, __shfl_xor_sync(0xffffffffu, mx, 2));
            mx = fmaxf(mx, __shfl_xor_sync(0xffffffffu, mx, 4));
            mx = fmaxf(mx, __shfl_xor_sync(0xffffffffu, mx, 8));
            const float mnew = fmaxf(mrow[i], mx);
            const float alpha = __expf(mrow[i] - mnew);
            mrow[i] = mnew;
            float rs = 0.f;
#pragma unroll
            for (int j = 0; j < 4; j++) {
                s[i][j] = __expf(s[i][j] - mnew);
                rs += s[i][j];
            }
            rs += __shfl_xor_sync(0xffffffffu, rs, 1);
            rs += __shfl_xor_sync(0xffffffffu, rs, 2);
            rs += __shfl_xor_sync(0xffffffffu, rs, 4);
            rs += __shfl_xor_sync(0xffffffffu, rs, 8);
            lrow[i] = lrow[i] * alpha + rs;
#pragma unroll
            for (int j = 0; j < 4; j++) O[i][j] *= alpha;
        }

        __syncthreads();   // everyone done reading K from KPs
        // Write P into KPs
#pragma unroll
        for (int i = 0; i < 4; i++)
#pragma unroll
            for (int j = 0; j < 4; j++)
                KPs[(ty + 16 * i) * SL + tx + 16 * j] = s[i][j];
        __syncthreads();

        // O += P @ V
        for (int kk = 0; kk < 64; kk++) {
            float p[4], v[4];
#pragma unroll
            for (int i = 0; i < 4; i++) p[i] = KPs[(ty + 16 * i) * SL + kk];
#pragma unroll
            for (int j = 0; j < 4; j++) v[j] = Vs[kk * SL + tx + 16 * j];
#pragma unroll
            for (int i = 0; i < 4; i++)
#pragma unroll
                for (int j = 0; j < 4; j++)
                    O[i][j] = fmaf(p[i], v[j], O[i][j]);
        }
    }

    // Normalize and write ctx in [b, n, h*64+d] layout
    const int bb = bh >> 4;
    const int h  = bh & 15;
#pragma unroll
    for (int i = 0; i < 4; i++) {
        const float inv = 1.f / lrow[i];
        const int n = q0 + ty + 16 * i;
#pragma unroll
        for (int j = 0; j < 4; j++) {
            g_ctx[((size_t)(bb * N_ + n)) * C_ + h * 64 + tx + 16 * j] = O[i][j] * inv;
        }
    }
}

// ---------------------------------------------------------------------------
extern "C" void kernel_launch(void* const* d_in, const int* in_sizes, int n_in,
                              void* d_out, int out_size)
{
    const float* x      = (const float*)d_in[0];
    const float* w_qkv  = (const float*)d_in[1];
    const float* w_proj = (const float*)d_in[2];
    const float* b_proj = (const float*)d_in[3];
    float* out = (float*)d_out;

    cudaFuncSetAttribute(attn_kernel,
                         cudaFuncAttributeMaxDynamicSharedMemorySize, ATTN_SMEM);

    // 1) QKV projection: [8192,1024] @ [1024,3072] -> scatter q/k/v
    dim3 g1(3072 / 128, MROWS / 128);
    sgemm_kernel<0><<<g1, 256>>>(x, w_qkv, nullptr, nullptr, MROWS, 3 * C_, C_);

    // 2) Attention: 64 (b,h) pairs x 32 query tiles
    attn_kernel<<<dim3(N_ / 64, BHn), 256, ATTN_SMEM>>>();

    // 3) Output projection: g_ctx[8192,1024] @ [1024,1024] + bias
    dim3 g3(C_ / 128, MROWS / 128);
    sgemm_kernel<1><<<g3, 256>>>(nullptr, w_proj, b_proj, out, MROWS, C_, C_);
}

// round 3
// speedup vs baseline: 3.7450x; 3.7450x over previous
#include <cuda_runtime.h>
#include <cuda_bf16.h>
#include <math_constants.h>

// Problem constants
#define B_    4
#define N_    2048
#define C_    1024
#define H_    16
#define D_    64
#define BHn   (B_ * H_)          // 64
#define MROWS (B_ * N_)          // 8192

// Scratch (static device arrays; no allocation at runtime)
__device__ float g_q[(size_t)BHn * N_ * D_];     // [bh, n, d], pre-scaled by 1/sqrt(D)
__device__ float g_k[(size_t)BHn * N_ * D_];
__device__ float g_v[(size_t)BHn * N_ * D_];
__device__ float g_ctx[(size_t)MROWS * C_];      // [b, n, h*64+d]

// ---------------------------------------------------------------------------
// Helpers: tf32 convert + m16n8k8 tf32 mma
// ---------------------------------------------------------------------------
__device__ __forceinline__ unsigned f2tf(float x) {
    unsigned r;
    asm("cvt.rna.tf32.f32 %0, %1;" : "=r"(r) : "f"(x));
    return r;
}

__device__ __forceinline__ void mma_tf32(float* d,
    unsigned a0, unsigned a1, unsigned a2, unsigned a3,
    unsigned b0, unsigned b1)
{
    asm volatile(
        "mma.sync.aligned.m16n8k8.row.col.f32.tf32.tf32.f32 "
        "{%0,%1,%2,%3}, {%4,%5,%6,%7}, {%8,%9}, {%0,%1,%2,%3};"
        : "+f"(d[0]), "+f"(d[1]), "+f"(d[2]), "+f"(d[3])
        : "r"(a0), "r"(a1), "r"(a2), "r"(a3), "r"(b0), "r"(b1));
}

// ---------------------------------------------------------------------------
// TF32 tensor-core GEMM: C = A[M,K] @ B[K,N]. 128x128x32 tile, 256 threads.
// Warp grid 2(m) x 4(n); warp tile 64x32 via m16n8k8.
// MODE 0: scatter into g_q/g_k/g_v (Q scaled by 0.125)
// MODE 1: A = g_ctx, epilogue adds bias, writes Cout
// Smem pitches: As 36 (=4 mod 32, conflict-free for 8row x 4col frag pattern),
//               Bs 136 (=8 mod 32, conflict-free for 4row x 8col frag pattern)
// ---------------------------------------------------------------------------
template <int MODE>
__global__ __launch_bounds__(256) void mma_gemm(
    const float* __restrict__ A, const float* __restrict__ Bm,
    const float* __restrict__ bias, float* __restrict__ Cout,
    int M, int Nn, int K)
{
    __shared__ unsigned As[128][36];
    __shared__ unsigned Bs[32][136];

    const int tid  = threadIdx.x;
    const int lane = tid & 31;
    const int wid  = tid >> 5;
    const int wm = (wid & 1) * 64;
    const int wn = (wid >> 1) * 32;
    const int r = lane >> 2;
    const int c = lane & 3;
    const int mBase = blockIdx.y * 128;
    const int nBase = blockIdx.x * 128;

    const float* Aptr = (MODE == 1 ? (const float*)g_ctx : A);

    float acc[4][4][4];
#pragma unroll
    for (int mi = 0; mi < 4; mi++)
#pragma unroll
        for (int ni = 0; ni < 4; ni++)
#pragma unroll
            for (int j = 0; j < 4; j++) acc[mi][ni][j] = 0.f;

    for (int kt = 0; kt < K; kt += 32) {
        float4 av[4], bv[4];
#pragma unroll
        for (int i = 0; i < 4; i++) {
            const int idx = tid + i * 256;
            const int arow = idx >> 3, ac4 = (idx & 7) * 4;
            av[i] = *(const float4*)&Aptr[(size_t)(mBase + arow) * K + kt + ac4];
            const int brow = idx >> 5, bc4 = (idx & 31) * 4;
            bv[i] = *(const float4*)&Bm[(size_t)(kt + brow) * Nn + nBase + bc4];
        }
        __syncthreads();
#pragma unroll
        for (int i = 0; i < 4; i++) {
            const int idx = tid + i * 256;
            const int arow = idx >> 3, ac4 = (idx & 7) * 4;
            As[arow][ac4 + 0] = f2tf(av[i].x);
            As[arow][ac4 + 1] = f2tf(av[i].y);
            As[arow][ac4 + 2] = f2tf(av[i].z);
            As[arow][ac4 + 3] = f2tf(av[i].w);
            const int brow = idx >> 5, bc4 = (idx & 31) * 4;
            Bs[brow][bc4 + 0] = f2tf(bv[i].x);
            Bs[brow][bc4 + 1] = f2tf(bv[i].y);
            Bs[brow][bc4 + 2] = f2tf(bv[i].z);
            Bs[brow][bc4 + 3] = f2tf(bv[i].w);
        }
        __syncthreads();

#pragma unroll
        for (int ks = 0; ks < 4; ks++) {
            const int k0 = ks * 8;
            unsigned a[4][4], b[4][2];
#pragma unroll
            for (int mi = 0; mi < 4; mi++) {
                const int m = wm + mi * 16;
                a[mi][0] = As[m + r][k0 + c];
                a[mi][1] = As[m + r + 8][k0 + c];
                a[mi][2] = As[m + r][k0 + c + 4];
                a[mi][3] = As[m + r + 8][k0 + c + 4];
            }
#pragma unroll
            for (int ni = 0; ni < 4; ni++) {
                const int n = wn + ni * 8 + r;
                b[ni][0] = Bs[k0 + c][n];
                b[ni][1] = Bs[k0 + c + 4][n];
            }
#pragma unroll
            for (int mi = 0; mi < 4; mi++)
#pragma unroll
                for (int ni = 0; ni < 4; ni++)
                    mma_tf32(acc[mi][ni], a[mi][0], a[mi][1], a[mi][2], a[mi][3],
                             b[ni][0], b[ni][1]);
        }
    }

    // Epilogue: each (mi,ni) block -> rows (row0,row0+8), col pair (col,col+1)
#pragma unroll
    for (int mi = 0; mi < 4; mi++) {
        const int row0 = mBase + wm + mi * 16 + r;
#pragma unroll
        for (int ni = 0; ni < 4; ni++) {
            const int col = nBase + wn + ni * 8 + 2 * c;
#pragma unroll
            for (int hh = 0; hh < 2; hh++) {
                const int m = row0 + hh * 8;
                float v0 = acc[mi][ni][2 * hh + 0];
                float v1 = acc[mi][ni][2 * hh + 1];
                if (MODE == 0) {
                    const int which = col >> 10;
                    const int cc = col & 1023;
                    const int h = cc >> 6;
                    const int d = cc & 63;
                    const int bb = m >> 11;
                    const int nn = m & 2047;
                    const size_t off = (((size_t)(bb * H_ + h)) * N_ + nn) * D_ + d;
                    float2 w;
                    if (which == 0) { w.x = v0 * 0.125f; w.y = v1 * 0.125f;
                                      *(float2*)&g_q[off] = w; }
                    else if (which == 1) { w.x = v0; w.y = v1;
                                      *(float2*)&g_k[off] = w; }
                    else { w.x = v0; w.y = v1;
                                      *(float2*)&g_v[off] = w; }
                } else {
                    float2 w = { v0 + bias[col], v1 + bias[col + 1] };
                    *(float2*)&Cout[(size_t)m * Nn + col] = w;
                }
            }
        }
    }
}

// ---------------------------------------------------------------------------
// TF32 tensor-core flash attention.
// CTA: 128 q rows, 8 warps x 16 q rows. K-tile 64, D=64.
// S via mma (fp32 acc), register online softmax, P rebuilt into A-fragments
// via quad shuffles (no P smem), PV via mma.
// Smem: Qs[128][68], Ks[64][68], Vs[64][72]  (pitch 68 = 4 mod 32 for
// 8rx4c frag pattern; 72 = 8 mod 32 for 4rx8c pattern).
// ---------------------------------------------------------------------------
#define QS_PITCH 68
#define KS_PITCH 68
#define VS_PITCH 72
#define ATTN_SMEM ((128 * QS_PITCH + 64 * KS_PITCH + 64 * VS_PITCH) * 4)

__global__ __launch_bounds__(256) void mma_attn()
{
    extern __shared__ unsigned smu[];
    unsigned* Qs = smu;                       // [128][68]
    unsigned* Ks = smu + 128 * QS_PITCH;      // [64][68]
    unsigned* Vs = Ks + 64 * KS_PITCH;        // [64][72]

    const int bh = blockIdx.y;
    const int q0 = blockIdx.x * 128;
    const int tid = threadIdx.x;
    const int lane = tid & 31;
    const int wid = tid >> 5;
    const int r = lane >> 2;
    const int c = lane & 3;
    const int qw = wid * 16;

    const float* Qg = g_q + (size_t)bh * N_ * D_;
    const float* Kg = g_k + (size_t)bh * N_ * D_;
    const float* Vg = g_v + (size_t)bh * N_ * D_;

    // Load Q tile (128x64) -> tf32 smem
#pragma unroll
    for (int i = 0; i < 8; i++) {
        const int idx = tid + i * 256;
        const int row = idx >> 4;
        const int c4 = (idx & 15) * 4;
        float4 v = *(const float4*)&Qg[(size_t)(q0 + row) * D_ + c4];
        Qs[row * QS_PITCH + c4 + 0] = f2tf(v.x);
        Qs[row * QS_PITCH + c4 + 1] = f2tf(v.y);
        Qs[row * QS_PITCH + c4 + 2] = f2tf(v.z);
        Qs[row * QS_PITCH + c4 + 3] = f2tf(v.w);
    }

    float m0 = -CUDART_INF_F, m1 = -CUDART_INF_F, l0 = 0.f, l1 = 0.f;
    float O[8][4];
#pragma unroll
    for (int nb = 0; nb < 8; nb++)
#pragma unroll
        for (int j = 0; j < 4; j++) O[nb][j] = 0.f;

    for (int kt = 0; kt < N_; kt += 64) {
        __syncthreads();
#pragma unroll
        for (int i = 0; i < 4; i++) {
            const int idx = tid + i * 256;
            const int row = idx >> 4;
            const int c4 = (idx & 15) * 4;
            float4 kv = *(const float4*)&Kg[(size_t)(kt + row) * D_ + c4];
            Ks[row * KS_PITCH + c4 + 0] = f2tf(kv.x);
            Ks[row * KS_PITCH + c4 + 1] = f2tf(kv.y);
            Ks[row * KS_PITCH + c4 + 2] = f2tf(kv.z);
            Ks[row * KS_PITCH + c4 + 3] = f2tf(kv.w);
            float4 vv = *(const float4*)&Vg[(size_t)(kt + row) * D_ + c4];
            Vs[row * VS_PITCH + c4 + 0] = f2tf(vv.x);
            Vs[row * VS_PITCH + c4 + 1] = f2tf(vv.y);
            Vs[row * VS_PITCH + c4 + 2] = f2tf(vv.z);
            Vs[row * VS_PITCH + c4 + 3] = f2tf(vv.w);
        }
        __syncthreads();

        // S = Q @ K^T  (warp: 16 q rows x 64 keys, 8 n-blocks)
        float s[8][4];
#pragma unroll
        for (int nb = 0; nb < 8; nb++)
#pragma unroll
            for (int j = 0; j < 4; j++) s[nb][j] = 0.f;

#pragma unroll
        for (int ks = 0; ks < 8; ks++) {
            const int k0 = ks * 8;
            unsigned a0 = Qs[(qw + r) * QS_PITCH + k0 + c];
            unsigned a1 = Qs[(qw + r + 8) * QS_PITCH + k0 + c];
            unsigned a2 = Qs[(qw + r) * QS_PITCH + k0 + c + 4];
            unsigned a3 = Qs[(qw + r + 8) * QS_PITCH + k0 + c + 4];
#pragma unroll
            for (int nb = 0; nb < 8; nb++) {
                unsigned b0 = Ks[(nb * 8 + r) * KS_PITCH + k0 + c];
                unsigned b1 = Ks[(nb * 8 + r) * KS_PITCH + k0 + c + 4];
                mma_tf32(s[nb], a0, a1, a2, a3, b0, b1);
            }
        }

        // Online softmax (rows r and r+8 per thread; quad = lanes sharing row)
        float mx0 = -CUDART_INF_F, mx1 = -CUDART_INF_F;
#pragma unroll
        for (int nb = 0; nb < 8; nb++) {
            mx0 = fmaxf(mx0, fmaxf(s[nb][0], s[nb][1]));
            mx1 = fmaxf(mx1, fmaxf(s[nb][2], s[nb][3]));
        }
        mx0 = fmaxf(mx0, __shfl_xor_sync(0xffffffffu, mx0, 1));
        mx0 = fmaxf(mx0, __shfl_xor_sync(0xffffffffu, mx0, 2));
        mx1 = fmaxf(mx1, __shfl_xor_sync(0xffffffffu, mx1, 1));
        mx1 = fmaxf(mx1, __shfl_xor_sync(0xffffffffu, mx1, 2));
        const float mn0 = fmaxf(m0, mx0);
        const float mn1 = fmaxf(m1, mx1);
        const float al0 = __expf(m0 - mn0);
        const float al1 = __expf(m1 - mn1);
        m0 = mn0; m1 = mn1;
        float rs0 = 0.f, rs1 = 0.f;
#pragma unroll
        for (int nb = 0; nb < 8; nb++) {
            s[nb][0] = __expf(s[nb][0] - mn0);
            s[nb][1] = __expf(s[nb][1] - mn0);
            rs0 += s[nb][0] + s[nb][1];
            s[nb][2] = __expf(s[nb][2] - mn1);
            s[nb][3] = __expf(s[nb][3] - mn1);
            rs1 += s[nb][2] + s[nb][3];
        }
        rs0 += __shfl_xor_sync(0xffffffffu, rs0, 1);
        rs0 += __shfl_xor_sync(0xffffffffu, rs0, 2);
        rs1 += __shfl_xor_sync(0xffffffffu, rs1, 1);
        rs1 += __shfl_xor_sync(0xffffffffu, rs1, 2);
        l0 = l0 * al0 + rs0;
        l1 = l1 * al1 + rs1;
#pragma unroll
        for (int nb = 0; nb < 8; nb++) {
            O[nb][0] *= al0; O[nb][1] *= al0;
            O[nb][2] *= al1; O[nb][3] *= al1;
        }

        // P -> tf32 registers
        unsigned pt[8][4];
#pragma unroll
        for (int nb = 0; nb < 8; nb++)
#pragma unroll
            for (int j = 0; j < 4; j++) pt[nb][j] = f2tf(s[nb][j]);

        // O += P @ V : rebuild A-frags from accumulator layout via quad shfl
        const int ls  = (r << 2) | (c >> 1);
        const int ls2 = ls | 2;     // (c>>1) in {0,1} -> +2 stays in quad
        const bool odd = (c & 1);
#pragma unroll
        for (int ks = 0; ks < 8; ks++) {
            const int k0 = ks * 8;
            unsigned q0v = __shfl_sync(0xffffffffu, pt[ks][0], ls);
            unsigned q1v = __shfl_sync(0xffffffffu, pt[ks][1], ls);
            unsigned q2v = __shfl_sync(0xffffffffu, pt[ks][2], ls);
            unsigned q3v = __shfl_sync(0xffffffffu, pt[ks][3], ls);
            unsigned u0v = __shfl_sync(0xffffffffu, pt[ks][0], ls2);
            unsigned u1v = __shfl_sync(0xffffffffu, pt[ks][1], ls2);
            unsigned u2v = __shfl_sync(0xffffffffu, pt[ks][2], ls2);
            unsigned u3v = __shfl_sync(0xffffffffu, pt[ks][3], ls2);
            unsigned a0 = odd ? q1v : q0v;
            unsigned a1 = odd ? q3v : q2v;
            unsigned a2 = odd ? u1v : u0v;
            unsigned a3 = odd ? u3v : u2v;
#pragma unroll
            for (int nb = 0; nb < 8; nb++) {
                unsigned b0 = Vs[(k0 + c) * VS_PITCH + nb * 8 + r];
                unsigned b1 = Vs[(k0 + 4 + c) * VS_PITCH + nb * 8 + r];
                mma_tf32(O[nb], a0, a1, a2, a3, b0, b1);
            }
        }
    }

    // Normalize + write ctx [b, n, h*64+d]
    const float inv0 = 1.f / l0;
    const float inv1 = 1.f / l1;
    const int bb = bh >> 4;
    const int h = bh & 15;
    const int row0 = q0 + qw + r;
    const int row1 = row0 + 8;
#pragma unroll
    for (int nb = 0; nb < 8; nb++) {
        const int col = h * 64 + nb * 8 + 2 * c;
        float2 w0 = { O[nb][0] * inv0, O[nb][1] * inv0 };
        float2 w1 = { O[nb][2] * inv1, O[nb][3] * inv1 };
        *(float2*)&g_ctx[((size_t)(bb * N_ + row0)) * C_ + col] = w0;
        *(float2*)&g_ctx[((size_t)(bb * N_ + row1)) * C_ + col] = w1;
    }
}

// ---------------------------------------------------------------------------
extern "C" void kernel_launch(void* const* d_in, const int* in_sizes, int n_in,
                              void* d_out, int out_size)
{
    const float* x      = (const float*)d_in[0];
    const float* w_qkv  = (const float*)d_in[1];
    const float* w_proj = (const float*)d_in[2];
    const float* b_proj = (const float*)d_in[3];
    float* out = (float*)d_out;

    cudaFuncSetAttribute(mma_attn,
                         cudaFuncAttributeMaxDynamicSharedMemorySize, ATTN_SMEM);

    // 1) QKV projection: [8192,1024] @ [1024,3072] -> scatter q/k/v (tf32)
    dim3 g1(3072 / 128, MROWS / 128);
    mma_gemm<0><<<g1, 256>>>(x, w_qkv, nullptr, nullptr, MROWS, 3 * C_, C_);

    // 2) Attention: 16 q-tiles x 64 (b,h)
    mma_attn<<<dim3(N_ / 128, BHn), 256, ATTN_SMEM>>>();

    // 3) Output projection: g_ctx[8192,1024] @ [1024,1024] + bias (tf32)
    dim3 g3(C_ / 128, MROWS / 128);
    mma_gemm<1><<<g3, 256>>>(nullptr, w_proj, b_proj, out, MROWS, C_, C_);
}

// round 4
// speedup vs baseline: 4.5145x; 1.2055x over previous
#include <cuda_runtime.h>
#include <cuda_bf16.h>
#include <math_constants.h>

// Problem constants
#define B_    4
#define N_    2048
#define C_    1024
#define H_    16
#define D_    64
#define BHn   (B_ * H_)          // 64
#define MROWS (B_ * N_)          // 8192

// Scratch (static device arrays; no runtime allocation)
__device__ float g_q[(size_t)BHn * N_ * D_];     // tf32-rounded, Q pre-scaled
__device__ float g_k[(size_t)BHn * N_ * D_];
__device__ float g_v[(size_t)BHn * N_ * D_];
__device__ float g_ctx[(size_t)MROWS * C_];      // tf32-rounded
__device__ float g_xr[(size_t)MROWS * C_];       // tf32-rounded x
__device__ float g_wqkv[(size_t)C_ * 3 * C_];    // tf32-rounded w_qkv
__device__ float g_wproj[(size_t)C_ * C_];       // tf32-rounded w_proj

// ---------------------------------------------------------------------------
// Helpers
// ---------------------------------------------------------------------------
__device__ __forceinline__ unsigned f2tf(float x) {
    unsigned r;
    asm("cvt.rna.tf32.f32 %0, %1;" : "=r"(r) : "f"(x));
    return r;
}

__device__ __forceinline__ void mma_tf32(float* d,
    unsigned a0, unsigned a1, unsigned a2, unsigned a3,
    unsigned b0, unsigned b1)
{
    asm volatile(
        "mma.sync.aligned.m16n8k8.row.col.f32.tf32.tf32.f32 "
        "{%0,%1,%2,%3}, {%4,%5,%6,%7}, {%8,%9}, {%0,%1,%2,%3};"
        : "+f"(d[0]), "+f"(d[1]), "+f"(d[2]), "+f"(d[3])
        : "r"(a0), "r"(a1), "r"(a2), "r"(a3), "r"(b0), "r"(b1));
}

__device__ __forceinline__ unsigned smem_u32(const void* p) {
    return (unsigned)__cvta_generic_to_shared(p);
}
__device__ __forceinline__ void cpa16(unsigned s, const void* g) {
    asm volatile("cp.async.cg.shared.global [%0], [%1], 16;" :: "r"(s), "l"(g));
}
#define CP_COMMIT() asm volatile("cp.async.commit_group;")
#define CP_WAIT1()  asm volatile("cp.async.wait_group 1;")

// ---------------------------------------------------------------------------
// Pre-rounding pass: fp32 -> tf32 (rna), stored as fp32 bits
// ---------------------------------------------------------------------------
__global__ void round_tf32_kernel(const float4* __restrict__ in,
                                  float4* __restrict__ out, int n4)
{
    int i = blockIdx.x * blockDim.x + threadIdx.x;
    if (i < n4) {
        float4 v = in[i];
        float4 w;
        w.x = __uint_as_float(f2tf(v.x));
        w.y = __uint_as_float(f2tf(v.y));
        w.z = __uint_as_float(f2tf(v.z));
        w.w = __uint_as_float(f2tf(v.w));
        out[i] = w;
    }
}

// ---------------------------------------------------------------------------
// TF32 GEMM, cp.async 3-stage pipeline. 128x128x32 tile, 256 threads,
// warp grid 2(m) x 4(n), warp tile 64x32 via m16n8k8.
// Inputs must be tf32-pre-rounded (no cvt in mainloop).
// MODE 0: scatter g_q/g_k/g_v (tf32-rounded, Q scaled). MODE 1: +bias -> Cout.
// ---------------------------------------------------------------------------
#define GA_PITCH 36
#define GB_PITCH 136
#define G_STAGE_WORDS (128 * GA_PITCH + 32 * GB_PITCH)   // 8960
#define G_SMEM (3 * G_STAGE_WORDS * 4)                   // 107520 B

template <int MODE>
__global__ __launch_bounds__(256, 2) void mma_gemm(
    const float* __restrict__ A, const float* __restrict__ Bm,
    const float* __restrict__ bias, float* __restrict__ Cout,
    int M, int Nn, int K)
{
    extern __shared__ unsigned gsm[];

    const int tid  = threadIdx.x;
    const int lane = tid & 31;
    const int wid  = tid >> 5;
    const int wm = (wid & 1) * 64;
    const int wn = (wid >> 1) * 32;
    const int r = lane >> 2;
    const int c = lane & 3;
    const int mBase = blockIdx.y * 128;
    const int nBase = blockIdx.x * 128;

    const float* Aptr = (MODE == 1 ? (const float*)g_ctx : A);

    auto issue_tile = [&](int kt, int stg) {
        const unsigned base = stg * G_STAGE_WORDS;
#pragma unroll
        for (int i = 0; i < 4; i++) {
            const int idx = tid + i * 256;
            const int arow = idx >> 3, ac4 = (idx & 7) * 4;
            cpa16(smem_u32(&gsm[base + arow * GA_PITCH + ac4]),
                  &Aptr[(size_t)(mBase + arow) * K + kt + ac4]);
        }
#pragma unroll
        for (int i = 0; i < 4; i++) {
            const int idx = tid + i * 256;
            const int brow = idx >> 5, bc4 = (idx & 31) * 4;
            cpa16(smem_u32(&gsm[base + 128 * GA_PITCH + brow * GB_PITCH + bc4]),
                  &Bm[(size_t)(kt + brow) * Nn + nBase + bc4]);
        }
    };

    float acc[4][4][4];
#pragma unroll
    for (int mi = 0; mi < 4; mi++)
#pragma unroll
        for (int ni = 0; ni < 4; ni++)
#pragma unroll
            for (int j = 0; j < 4; j++) acc[mi][ni][j] = 0.f;

    const int nT = K / 32;
    issue_tile(0, 0);  CP_COMMIT();
    issue_tile(32, 1); CP_COMMIT();

    for (int t = 0; t < nT; t++) {
        CP_WAIT1();
        __syncthreads();
        const unsigned* As_ = gsm + (t % 3) * G_STAGE_WORDS;
        const unsigned* Bs_ = As_ + 128 * GA_PITCH;

#pragma unroll
        for (int ks = 0; ks < 4; ks++) {
            const int k0 = ks * 8;
            unsigned a[4][4], b[4][2];
#pragma unroll
            for (int mi = 0; mi < 4; mi++) {
                const int m = wm + mi * 16;
                a[mi][0] = As_[(m + r) * GA_PITCH + k0 + c];
                a[mi][1] = As_[(m + r + 8) * GA_PITCH + k0 + c];
                a[mi][2] = As_[(m + r) * GA_PITCH + k0 + c + 4];
                a[mi][3] = As_[(m + r + 8) * GA_PITCH + k0 + c + 4];
            }
#pragma unroll
            for (int ni = 0; ni < 4; ni++) {
                const int n = wn + ni * 8 + r;
                b[ni][0] = Bs_[(k0 + c) * GB_PITCH + n];
                b[ni][1] = Bs_[(k0 + c + 4) * GB_PITCH + n];
            }
#pragma unroll
            for (int mi = 0; mi < 4; mi++)
#pragma unroll
                for (int ni = 0; ni < 4; ni++)
                    mma_tf32(acc[mi][ni], a[mi][0], a[mi][1], a[mi][2], a[mi][3],
                             b[ni][0], b[ni][1]);
        }

        if (t + 2 < nT) issue_tile((t + 2) * 32, (t + 2) % 3);
        CP_COMMIT();
    }

    // Epilogue
#pragma unroll
    for (int mi = 0; mi < 4; mi++) {
        const int row0 = mBase + wm + mi * 16 + r;
#pragma unroll
        for (int ni = 0; ni < 4; ni++) {
            const int col = nBase + wn + ni * 8 + 2 * c;
#pragma unroll
            for (int hh = 0; hh < 2; hh++) {
                const int m = row0 + hh * 8;
                float v0 = acc[mi][ni][2 * hh + 0];
                float v1 = acc[mi][ni][2 * hh + 1];
                if (MODE == 0) {
                    const int which = col >> 10;
                    const int cc = col & 1023;
                    const int h = cc >> 6;
                    const int d = cc & 63;
                    const int bb = m >> 11;
                    const int nn = m & 2047;
                    const size_t off = (((size_t)(bb * H_ + h)) * N_ + nn) * D_ + d;
                    float2 w;
                    if (which == 0) {
                        w.x = __uint_as_float(f2tf(v0 * 0.125f));
                        w.y = __uint_as_float(f2tf(v1 * 0.125f));
                        *(float2*)&g_q[off] = w;
                    } else if (which == 1) {
                        w.x = __uint_as_float(f2tf(v0));
                        w.y = __uint_as_float(f2tf(v1));
                        *(float2*)&g_k[off] = w;
                    } else {
                        w.x = __uint_as_float(f2tf(v0));
                        w.y = __uint_as_float(f2tf(v1));
                        *(float2*)&g_v[off] = w;
                    }
                } else {
                    float2 w = { v0 + bias[col], v1 + bias[col + 1] };
                    *(float2*)&Cout[(size_t)m * Nn + col] = w;
                }
            }
        }
    }
}

// ---------------------------------------------------------------------------
// TF32 flash attention, cp.async 3-stage K/V pipeline.
// CTA: 128 q rows, 8 warps x 16 q rows; k-tile 64; D=64.
// Q fragments live in registers (loaded once from pre-rounded g_q).
// Register online softmax; P rebuilt into A-frags via quad shuffles.
// ---------------------------------------------------------------------------
#define KS_PITCH 68
#define VS_PITCH 72
#define A_STAGE_WORDS (64 * KS_PITCH + 64 * VS_PITCH)   // 8960
#define ATTN_SMEM (3 * A_STAGE_WORDS * 4)               // 107520 B

__global__ __launch_bounds__(256, 2) void mma_attn()
{
    extern __shared__ unsigned smu[];

    const int bh = blockIdx.y;
    const int q0 = blockIdx.x * 128;
    const int tid = threadIdx.x;
    const int lane = tid & 31;
    const int wid = tid >> 5;
    const int r = lane >> 2;
    const int c = lane & 3;
    const int qw = wid * 16;

    const float* Kg = g_k + (size_t)bh * N_ * D_;
    const float* Vg = g_v + (size_t)bh * N_ * D_;

    auto issue_kv = [&](int kt, int stg) {
        const unsigned base = stg * A_STAGE_WORDS;
#pragma unroll
        for (int i = 0; i < 4; i++) {
            const int idx = tid + i * 256;
            const int row = idx >> 4;
            const int c4 = (idx & 15) * 4;
            cpa16(smem_u32(&smu[base + row * KS_PITCH + c4]),
                  &Kg[(size_t)(kt + row) * D_ + c4]);
            cpa16(smem_u32(&smu[base + 64 * KS_PITCH + row * VS_PITCH + c4]),
                  &Vg[(size_t)(kt + row) * D_ + c4]);
        }
    };

    // Q fragments -> registers (g_q is tf32-pre-rounded and pre-scaled)
    unsigned qa[8][4];
    {
        const float* Qr0 = g_q + (size_t)bh * N_ * D_ + (size_t)(q0 + qw + r) * D_;
        const float* Qr1 = Qr0 + 8 * D_;
#pragma unroll
        for (int ks = 0; ks < 8; ks++) {
            const int k0 = ks * 8;
            qa[ks][0] = __float_as_uint(Qr0[k0 + c]);
            qa[ks][1] = __float_as_uint(Qr1[k0 + c]);
            qa[ks][2] = __float_as_uint(Qr0[k0 + c + 4]);
            qa[ks][3] = __float_as_uint(Qr1[k0 + c + 4]);
        }
    }

    float m0 = -CUDART_INF_F, m1 = -CUDART_INF_F, l0 = 0.f, l1 = 0.f;
    float O[8][4];
#pragma unroll
    for (int nb = 0; nb < 8; nb++)
#pragma unroll
        for (int j = 0; j < 4; j++) O[nb][j] = 0.f;

    const int nT = N_ / 64;   // 32
    issue_kv(0, 0);  CP_COMMIT();
    issue_kv(64, 1); CP_COMMIT();

    const int ls  = (r << 2) | (c >> 1);
    const int ls2 = ls | 2;
    const bool odd = (c & 1);

    for (int t = 0; t < nT; t++) {
        CP_WAIT1();
        __syncthreads();
        const unsigned* Ks_ = smu + (t % 3) * A_STAGE_WORDS;
        const unsigned* Vs_ = Ks_ + 64 * KS_PITCH;

        // S = Q @ K^T
        float s[8][4];
#pragma unroll
        for (int nb = 0; nb < 8; nb++)
#pragma unroll
            for (int j = 0; j < 4; j++) s[nb][j] = 0.f;

#pragma unroll
        for (int ks = 0; ks < 8; ks++) {
            const int k0 = ks * 8;
#pragma unroll
            for (int nb = 0; nb < 8; nb++) {
                unsigned b0 = Ks_[(nb * 8 + r) * KS_PITCH + k0 + c];
                unsigned b1 = Ks_[(nb * 8 + r) * KS_PITCH + k0 + c + 4];
                mma_tf32(s[nb], qa[ks][0], qa[ks][1], qa[ks][2], qa[ks][3], b0, b1);
            }
        }

        // Online softmax (rows r, r+8; quad reduction)
        float mx0 = -CUDART_INF_F, mx1 = -CUDART_INF_F;
#pragma unroll
        for (int nb = 0; nb < 8; nb++) {
            mx0 = fmaxf(mx0, fmaxf(s[nb][0], s[nb][1]));
            mx1 = fmaxf(mx1, fmaxf(s[nb][2], s[nb][3]));
        }
        mx0 = fmaxf(mx0, __shfl_xor_sync(0xffffffffu, mx0, 1));
        mx0 = fmaxf(mx0, __shfl_xor_sync(0xffffffffu, mx0, 2));
        mx1 = fmaxf(mx1, __shfl_xor_sync(0xffffffffu, mx1, 1));
        mx1 = fmaxf(mx1, __shfl_xor_sync(0xffffffffu, mx1, 2));
        const float mn0 = fmaxf(m0, mx0);
        const float mn1 = fmaxf(m1, mx1);
        const float al0 = __expf(m0 - mn0);
        const float al1 = __expf(m1 - mn1);
        m0 = mn0; m1 = mn1;
        float rs0 = 0.f, rs1 = 0.f;
#pragma unroll
        for (int nb = 0; nb < 8; nb++) {
            s[nb][0] = __expf(s[nb][0] - mn0);
            s[nb][1] = __expf(s[nb][1] - mn0);
            rs0 += s[nb][0] + s[nb][1];
            s[nb][2] = __expf(s[nb][2] - mn1);
            s[nb][3] = __expf(s[nb][3] - mn1);
            rs1 += s[nb][2] + s[nb][3];
        }
        rs0 += __shfl_xor_sync(0xffffffffu, rs0, 1);
        rs0 += __shfl_xor_sync(0xffffffffu, rs0, 2);
        rs1 += __shfl_xor_sync(0xffffffffu, rs1, 1);
        rs1 += __shfl_xor_sync(0xffffffffu, rs1, 2);
        l0 = l0 * al0 + rs0;
        l1 = l1 * al1 + rs1;
#pragma unroll
        for (int nb = 0; nb < 8; nb++) {
            O[nb][0] *= al0; O[nb][1] *= al0;
            O[nb][2] *= al1; O[nb][3] *= al1;
        }

        // P -> tf32 regs
        unsigned pt[8][4];
#pragma unroll
        for (int nb = 0; nb < 8; nb++)
#pragma unroll
            for (int j = 0; j < 4; j++) pt[nb][j] = f2tf(s[nb][j]);

        // O += P @ V (A-frags via quad shuffles)
#pragma unroll
        for (int ks = 0; ks < 8; ks++) {
            const int k0 = ks * 8;
            unsigned q0v = __shfl_sync(0xffffffffu, pt[ks][0], ls);
            unsigned q1v = __shfl_sync(0xffffffffu, pt[ks][1], ls);
            unsigned q2v = __shfl_sync(0xffffffffu, pt[ks][2], ls);
            unsigned q3v = __shfl_sync(0xffffffffu, pt[ks][3], ls);
            unsigned u0v = __shfl_sync(0xffffffffu, pt[ks][0], ls2);
            unsigned u1v = __shfl_sync(0xffffffffu, pt[ks][1], ls2);
            unsigned u2v = __shfl_sync(0xffffffffu, pt[ks][2], ls2);
            unsigned u3v = __shfl_sync(0xffffffffu, pt[ks][3], ls2);
            unsigned a0 = odd ? q1v : q0v;
            unsigned a1 = odd ? q3v : q2v;
            unsigned a2 = odd ? u1v : u0v;
            unsigned a3 = odd ? u3v : u2v;
#pragma unroll
            for (int nb = 0; nb < 8; nb++) {
                unsigned b0 = Vs_[(k0 + c) * VS_PITCH + nb * 8 + r];
                unsigned b1 = Vs_[(k0 + 4 + c) * VS_PITCH + nb * 8 + r];
                mma_tf32(O[nb], a0, a1, a2, a3, b0, b1);
            }
        }

        if (t + 2 < nT) issue_kv((t + 2) * 64, (t + 2) % 3);
        CP_COMMIT();
    }

    // Normalize + write ctx (tf32-rounded for the proj GEMM's cp.async path)
    const float inv0 = 1.f / l0;
    const float inv1 = 1.f / l1;
    const int bb = bh >> 4;
    const int h = bh & 15;
    const int row0 = q0 + qw + r;
    const int row1 = row0 + 8;
#pragma unroll
    for (int nb = 0; nb < 8; nb++) {
        const int col = h * 64 + nb * 8 + 2 * c;
        float2 w0 = { __uint_as_float(f2tf(O[nb][0] * inv0)),
                      __uint_as_float(f2tf(O[nb][1] * inv0)) };
        float2 w1 = { __uint_as_float(f2tf(O[nb][2] * inv1)),
                      __uint_as_float(f2tf(O[nb][3] * inv1)) };
        *(float2*)&g_ctx[((size_t)(bb * N_ + row0)) * C_ + col] = w0;
        *(float2*)&g_ctx[((size_t)(bb * N_ + row1)) * C_ + col] = w1;
    }
}

// ---------------------------------------------------------------------------
extern "C" void kernel_launch(void* const* d_in, const int* in_sizes, int n_in,
                              void* d_out, int out_size)
{
    const float* x      = (const float*)d_in[0];
    const float* w_qkv  = (const float*)d_in[1];
    const float* w_proj = (const float*)d_in[2];
    const float* b_proj = (const float*)d_in[3];
    float* out = (float*)d_out;

    cudaFuncSetAttribute(mma_gemm<0>,
                         cudaFuncAttributeMaxDynamicSharedMemorySize, G_SMEM);
    cudaFuncSetAttribute(mma_gemm<1>,
                         cudaFuncAttributeMaxDynamicSharedMemorySize, G_SMEM);
    cudaFuncSetAttribute(mma_attn,
                         cudaFuncAttributeMaxDynamicSharedMemorySize, ATTN_SMEM);

    float* xr; float* wq; float* wp;
    cudaGetSymbolAddress((void**)&xr, g_xr);
    cudaGetSymbolAddress((void**)&wq, g_wqkv);
    cudaGetSymbolAddress((void**)&wp, g_wproj);

    // 0) tf32 pre-rounding passes
    {
        int n4x = MROWS * C_ / 4;
        round_tf32_kernel<<<n4x / 256, 256>>>((const float4*)x, (float4*)xr, n4x);
        int n4q = C_ * 3 * C_ / 4;
        round_tf32_kernel<<<n4q / 256, 256>>>((const float4*)w_qkv, (float4*)wq, n4q);
        int n4p = C_ * C_ / 4;
        round_tf32_kernel<<<n4p / 256, 256>>>((const float4*)w_proj, (float4*)wp, n4p);
    }

    // 1) QKV projection
    dim3 g1(3072 / 128, MROWS / 128);
    mma_gemm<0><<<g1, 256, G_SMEM>>>(xr, wq, nullptr, nullptr, MROWS, 3 * C_, C_);

    // 2) Attention
    mma_attn<<<dim3(N_ / 128, BHn), 256, ATTN_SMEM>>>();

    // 3) Output projection + bias
    dim3 g3(C_ / 128, MROWS / 128);
    mma_gemm<1><<<g3, 256, G_SMEM>>>(nullptr, wp, b_proj, out, MROWS, C_, C_);
}

// round 6
// speedup vs baseline: 4.7166x; 1.0448x over previous
#include <cuda_runtime.h>
#include <cuda_bf16.h>
#include <math_constants.h>
#include <cstdint>

// Problem constants
#define B_    4
#define N_    2048
#define C_    1024
#define H_    16
#define D_    64
#define BHn   (B_ * H_)          // 64
#define MROWS (B_ * N_)          // 8192

// Scratch (static device arrays; no runtime allocation)
__device__ float g_q[(size_t)BHn * N_ * D_];     // [bh][n][d], tf32-rounded, pre-scaled
__device__ float g_k[(size_t)BHn * N_ * D_];     // [bh][n][d], tf32-rounded
__device__ float g_v[(size_t)BHn * N_ * D_];     // [bh][d][n]  (TRANSPOSED), tf32-rounded
__device__ float g_ctx[(size_t)MROWS * C_];      // tf32-rounded
__device__ float g_xr[(size_t)MROWS * C_];       // tf32-rounded x
__device__ float g_wqkv[(size_t)3 * C_ * C_];    // w_qkv^T, tf32-rounded  [3072][1024]
__device__ float g_wproj[(size_t)C_ * C_];       // w_proj^T, tf32-rounded [1024][1024]

// ---------------------------------------------------------------------------
// Helpers
// ---------------------------------------------------------------------------
__device__ __forceinline__ unsigned f2tf(float x) {
    unsigned r;
    asm("cvt.rna.tf32.f32 %0, %1;" : "=r"(r) : "f"(x));
    return r;
}

__device__ __forceinline__ void mma_tf32(float* d,
    unsigned a0, unsigned a1, unsigned a2, unsigned a3,
    unsigned b0, unsigned b1)
{
    asm volatile(
        "mma.sync.aligned.m16n8k8.row.col.f32.tf32.tf32.f32 "
        "{%0,%1,%2,%3}, {%4,%5,%6,%7}, {%8,%9}, {%0,%1,%2,%3};"
        : "+f"(d[0]), "+f"(d[1]), "+f"(d[2]), "+f"(d[3])
        : "r"(a0), "r"(a1), "r"(a2), "r"(a3), "r"(b0), "r"(b1));
}

__device__ __forceinline__ unsigned smem_u32(const void* p) {
    return (unsigned)__cvta_generic_to_shared(p);
}
__device__ __forceinline__ void cpa16(unsigned s, const void* g) {
    asm volatile("cp.async.cg.shared.global [%0], [%1], 16;" :: "r"(s), "l"(g));
}
#define CP_COMMIT() asm volatile("cp.async.commit_group;")
#define CP_WAIT1()  asm volatile("cp.async.wait_group 1;")

// ldmatrix x4 on 32-bit data (b16 view; raw bits)
__device__ __forceinline__ void ldsm4(unsigned& r0, unsigned& r1,
                                      unsigned& r2, unsigned& r3, unsigned addr)
{
    asm volatile(
        "ldmatrix.sync.aligned.m8n8.x4.shared.b16 {%0,%1,%2,%3}, [%4];"
        : "=r"(r0), "=r"(r1), "=r"(r2), "=r"(r3) : "r"(addr));
}

// ---------------------------------------------------------------------------
// Pre-pass kernels
// ---------------------------------------------------------------------------
__global__ void round_tf32_kernel(const float4* __restrict__ in,
                                  float4* __restrict__ out, int n4)
{
    int i = blockIdx.x * blockDim.x + threadIdx.x;
    if (i < n4) {
        float4 v = in[i];
        float4 w;
        w.x = __uint_as_float(f2tf(v.x));
        w.y = __uint_as_float(f2tf(v.y));
        w.z = __uint_as_float(f2tf(v.z));
        w.w = __uint_as_float(f2tf(v.w));
        out[i] = w;
    }
}

// in [K][Nn] -> outT [Nn][K], tf32-rounded
__global__ void transpose_round_kernel(const float* __restrict__ in,
                                       float* __restrict__ outT, int K, int Nn)
{
    __shared__ float t[32][33];
    const int bx = blockIdx.x * 32;   // n
    const int by = blockIdx.y * 32;   // k
    const int x = threadIdx.x, y = threadIdx.y;
#pragma unroll
    for (int i = 0; i < 32; i += 8)
        t[y + i][x] = in[(size_t)(by + y + i) * Nn + bx + x];
    __syncthreads();
#pragma unroll
    for (int i = 0; i < 32; i += 8)
        outT[(size_t)(bx + y + i) * K + by + x] =
            __uint_as_float(f2tf(t[x][y + i]));
}

// ---------------------------------------------------------------------------
// TF32 GEMM via mma.sync + ldmatrix. D[m][n] = sum_k A[m][k] * Bt[n][k].
// 128x128x32 CTA tile, 256 threads, warp grid 2(m) x 4(n), warp tile 64x32.
// A and Bt tiles both k-major rows, pitch 36 (=4 mod 32: LDSM conflict-free).
// 3-stage cp.async ring, one __syncthreads per k-iter.
// MODE 0: scatter q/k/v (q scaled, v transposed). MODE 1: +bias -> Cout.
// ---------------------------------------------------------------------------
#define GP 36
#define G_STAGE_WORDS (128 * GP * 2)          // A + B = 9216 words
#define G_SMEM (3 * G_STAGE_WORDS * 4)        // 110592 B

template <int MODE>
__global__ __launch_bounds__(256, 2) void mma_gemm(
    const float* __restrict__ A, const float* __restrict__ Bt,
    const float* __restrict__ bias, float* __restrict__ Cout, int K)
{
    extern __shared__ unsigned gsm[];

    const int tid  = threadIdx.x;
    const int lane = tid & 31;
    const int wid  = tid >> 5;
    const int wm = (wid & 1) * 64;
    const int wn = (wid >> 1) * 32;
    const int r = lane >> 2;
    const int c = lane & 3;
    const int mBase = blockIdx.y * 128;
    const int nBase = blockIdx.x * 128;

    const float* Aptr = (MODE == 1) ? (const float*)g_ctx : A;

    // LDSM address offsets (words), per-thread
    const int mat = lane >> 3, mrr = lane & 7;
    int a_off[4], b_off[2];
#pragma unroll
    for (int mi = 0; mi < 4; mi++)
        a_off[mi] = (wm + mi * 16 + mrr + (mat & 1) * 8) * GP + (mat >> 1) * 4;
#pragma unroll
    for (int p = 0; p < 2; p++)
        b_off[p] = 128 * GP +
                   (wn + p * 16 + mrr + ((mat >> 1) & 1) * 8) * GP + (mat & 1) * 4;

    auto issue_tile = [&](int t) {
        const unsigned base = (t % 3) * G_STAGE_WORDS;
        const int kt = t * 32;
#pragma unroll
        for (int i = 0; i < 4; i++) {          // A: 128 rows x 8 chunks
            const int idx = tid + i * 256;
            const int row = idx >> 3, c4 = (idx & 7) * 4;
            cpa16(smem_u32(&gsm[base + row * GP + c4]),
                  &Aptr[(size_t)(mBase + row) * K + kt + c4]);
        }
#pragma unroll
        for (int i = 0; i < 4; i++) {          // Bt: 128 rows x 8 chunks
            const int idx = tid + i * 256;
            const int row = idx >> 3, c4 = (idx & 7) * 4;
            cpa16(smem_u32(&gsm[base + 128 * GP + row * GP + c4]),
                  &Bt[(size_t)(nBase + row) * K + kt + c4]);
        }
    };

    float acc[4][4][4];
#pragma unroll
    for (int mi = 0; mi < 4; mi++)
#pragma unroll
        for (int ni = 0; ni < 4; ni++)
#pragma unroll
            for (int j = 0; j < 4; j++) acc[mi][ni][j] = 0.f;

    const int nT = K / 32;
    issue_tile(0); CP_COMMIT();
    issue_tile(1); CP_COMMIT();

    for (int t = 0; t < nT; t++) {
        CP_WAIT1();
        __syncthreads();
        const unsigned sbase = smem_u32(gsm) + ((t % 3) * G_STAGE_WORDS) * 4;

#pragma unroll
        for (int ks = 0; ks < 4; ks++) {
            const int k0 = ks * 8;
            unsigned a[4][4], bt2[2][4];
#pragma unroll
            for (int mi = 0; mi < 4; mi++)
                ldsm4(a[mi][0], a[mi][1], a[mi][2], a[mi][3],
                      sbase + (a_off[mi] + k0) * 4);
#pragma unroll
            for (int p = 0; p < 2; p++)
                ldsm4(bt2[p][0], bt2[p][1], bt2[p][2], bt2[p][3],
                      sbase + (b_off[p] + k0) * 4);
#pragma unroll
            for (int mi = 0; mi < 4; mi++)
#pragma unroll
                for (int ni = 0; ni < 4; ni++)
                    mma_tf32(acc[mi][ni], a[mi][0], a[mi][1], a[mi][2], a[mi][3],
                             bt2[ni >> 1][(ni & 1) * 2],
                             bt2[ni >> 1][(ni & 1) * 2 + 1]);
        }

        if (t + 2 < nT) issue_tile(t + 2);
        CP_COMMIT();
    }

    // Epilogue
#pragma unroll
    for (int mi = 0; mi < 4; mi++) {
        const int row0 = mBase + wm + mi * 16 + r;
#pragma unroll
        for (int ni = 0; ni < 4; ni++) {
            const int col = nBase + wn + ni * 8 + 2 * c;
#pragma unroll
            for (int hh = 0; hh < 2; hh++) {
                const int m = row0 + hh * 8;
                float v0 = acc[mi][ni][2 * hh + 0];
                float v1 = acc[mi][ni][2 * hh + 1];
                if (MODE == 0) {
                    const int which = col >> 10;
                    const int cc = col & 1023;
                    const int h = cc >> 6;
                    const int d = cc & 63;
                    const int bb = m >> 11;
                    const int nn = m & 2047;
                    if (which == 0) {
                        float2 w = { __uint_as_float(f2tf(v0 * 0.125f)),
                                     __uint_as_float(f2tf(v1 * 0.125f)) };
                        *(float2*)&g_q[(((size_t)(bb * H_ + h)) * N_ + nn) * D_ + d] = w;
                    } else if (which == 1) {
                        float2 w = { __uint_as_float(f2tf(v0)),
                                     __uint_as_float(f2tf(v1)) };
                        *(float2*)&g_k[(((size_t)(bb * H_ + h)) * N_ + nn) * D_ + d] = w;
                    } else {
                        // V transposed: [bh][d][n]
                        const size_t vb = ((size_t)(bb * H_ + h)) * D_;
                        g_v[(vb + d) * N_ + nn]     = __uint_as_float(f2tf(v0));
                        g_v[(vb + d + 1) * N_ + nn] = __uint_as_float(f2tf(v1));
                    }
                } else {
                    float2 w = { v0 + bias[col], v1 + bias[col + 1] };
                    *(float2*)&Cout[(size_t)m * C_ + col] = w;
                }
            }
        }
    }
}

// ---------------------------------------------------------------------------
// TF32 flash attention with ldmatrix fragment feeds.
// CTA: 128 q rows, 8 warps x 16 q rows; k-tile 64; D=64.
// Q frags in registers; K tile [64 keys][68] k-major; V tile TRANSPOSED
// [64 d][68] (from g_v [bh][d][n]) so both S and PV B-frags come via LDSM.
// ---------------------------------------------------------------------------
#define KP 68
#define A_STAGE_WORDS (64 * KP * 2)             // 8704
#define ATTN_SMEM (3 * A_STAGE_WORDS * 4)       // 104448 B

__global__ __launch_bounds__(256, 2) void mma_attn()
{
    extern __shared__ unsigned smu[];

    const int bh = blockIdx.y;
    const int q0 = blockIdx.x * 128;
    const int tid = threadIdx.x;
    const int lane = tid & 31;
    const int wid = tid >> 5;
    const int r = lane >> 2;
    const int c = lane & 3;
    const int qw = wid * 16;

    const float* Kg = g_k + (size_t)bh * N_ * D_;
    const float* Vt = g_v + (size_t)bh * D_ * N_;   // [d][n]

    // LDSM offsets: 4 nb-pairs, B-pattern (row=n-dim, col=k-dim)
    const int mat = lane >> 3, mrr = lane & 7;
    int kb_off[4], vb_off[4];
#pragma unroll
    for (int p = 0; p < 4; p++) {
        const int rw = p * 16 + ((mat >> 1) & 1) * 8 + mrr;
        const int cl = (mat & 1) * 4;
        kb_off[p] = rw * KP + cl;
        vb_off[p] = 64 * KP + rw * KP + cl;
    }

    auto issue_kv = [&](int t) {
        const unsigned base = (t % 3) * A_STAGE_WORDS;
        const int kt = t * 64;
#pragma unroll
        for (int i = 0; i < 4; i++) {
            const int idx = tid + i * 256;
            const int row = idx >> 4;
            const int c4 = (idx & 15) * 4;
            cpa16(smem_u32(&smu[base + row * KP + c4]),
                  &Kg[(size_t)(kt + row) * D_ + c4]);          // K: [key][d]
            cpa16(smem_u32(&smu[base + 64 * KP + row * KP + c4]),
                  &Vt[(size_t)row * N_ + kt + c4]);            // V^T: [d][key]
        }
    };

    // Q fragments -> registers
    unsigned qa[8][4];
    {
        const float* Qr0 = g_q + (size_t)bh * N_ * D_ + (size_t)(q0 + qw + r) * D_;
        const float* Qr1 = Qr0 + 8 * D_;
#pragma unroll
        for (int ks = 0; ks < 8; ks++) {
            const int k0 = ks * 8;
            qa[ks][0] = __float_as_uint(Qr0[k0 + c]);
            qa[ks][1] = __float_as_uint(Qr1[k0 + c]);
            qa[ks][2] = __float_as_uint(Qr0[k0 + c + 4]);
            qa[ks][3] = __float_as_uint(Qr1[k0 + c + 4]);
        }
    }

    float m0 = -CUDART_INF_F, m1 = -CUDART_INF_F, l0 = 0.f, l1 = 0.f;
    float O[8][4];
#pragma unroll
    for (int nb = 0; nb < 8; nb++)
#pragma unroll
        for (int j = 0; j < 4; j++) O[nb][j] = 0.f;

    const int nT = N_ / 64;
    issue_kv(0); CP_COMMIT();
    issue_kv(1); CP_COMMIT();

    const int ls  = (r << 2) | (c >> 1);
    const int ls2 = ls | 2;
    const bool odd = (c & 1);

    for (int t = 0; t < nT; t++) {
        CP_WAIT1();
        __syncthreads();
        const unsigned sbase = smem_u32(smu) + ((t % 3) * A_STAGE_WORDS) * 4;

        // S = Q @ K^T
        float s[8][4];
#pragma unroll
        for (int nb = 0; nb < 8; nb++)
#pragma unroll
            for (int j = 0; j < 4; j++) s[nb][j] = 0.f;

#pragma unroll
        for (int ks = 0; ks < 8; ks++) {
            const int k0 = ks * 8;
            unsigned bt2[4][4];
#pragma unroll
            for (int p = 0; p < 4; p++)
                ldsm4(bt2[p][0], bt2[p][1], bt2[p][2], bt2[p][3],
                      sbase + (kb_off[p] + k0) * 4);
#pragma unroll
            for (int nb = 0; nb < 8; nb++)
                mma_tf32(s[nb], qa[ks][0], qa[ks][1], qa[ks][2], qa[ks][3],
                         bt2[nb >> 1][(nb & 1) * 2],
                         bt2[nb >> 1][(nb & 1) * 2 + 1]);
        }

        // Online softmax (rows r, r+8; quad reduction)
        float mx0 = -CUDART_INF_F, mx1 = -CUDART_INF_F;
#pragma unroll
        for (int nb = 0; nb < 8; nb++) {
            mx0 = fmaxf(mx0, fmaxf(s[nb][0], s[nb][1]));
            mx1 = fmaxf(mx1, fmaxf(s[nb][2], s[nb][3]));
        }
        mx0 = fmaxf(mx0, __shfl_xor_sync(0xffffffffu, mx0, 1));
        mx0 = fmaxf(mx0, __shfl_xor_sync(0xffffffffu, mx0, 2));
        mx1 = fmaxf(mx1, __shfl_xor_sync(0xffffffffu, mx1, 1));
        mx1 = fmaxf(mx1, __shfl_xor_sync(0xffffffffu, mx1, 2));
        const float mn0 = fmaxf(m0, mx0);
        const float mn1 = fmaxf(m1, mx1);
        const float al0 = __expf(m0 - mn0);
        const float al1 = __expf(m1 - mn1);
        m0 = mn0; m1 = mn1;
        float rs0 = 0.f, rs1 = 0.f;
#pragma unroll
        for (int nb = 0; nb < 8; nb++) {
            s[nb][0] = __expf(s[nb][0] - mn0);
            s[nb][1] = __expf(s[nb][1] - mn0);
            rs0 += s[nb][0] + s[nb][1];
            s[nb][2] = __expf(s[nb][2] - mn1);
            s[nb][3] = __expf(s[nb][3] - mn1);
            rs1 += s[nb][2] + s[nb][3];
        }
        rs0 += __shfl_xor_sync(0xffffffffu, rs0, 1);
        rs0 += __shfl_xor_sync(0xffffffffu, rs0, 2);
        rs1 += __shfl_xor_sync(0xffffffffu, rs1, 1);
        rs1 += __shfl_xor_sync(0xffffffffu, rs1, 2);
        l0 = l0 * al0 + rs0;
        l1 = l1 * al1 + rs1;
#pragma unroll
        for (int nb = 0; nb < 8; nb++) {
            O[nb][0] *= al0; O[nb][1] *= al0;
            O[nb][2] *= al1; O[nb][3] *= al1;
        }

        // P -> tf32 regs
        unsigned pt[8][4];
#pragma unroll
        for (int nb = 0; nb < 8; nb++)
#pragma unroll
            for (int j = 0; j < 4; j++) pt[nb][j] = f2tf(s[nb][j]);

        // O += P @ V : A-frags via quad shuffles, B-frags via LDSM on V^T
#pragma unroll
        for (int ks = 0; ks < 8; ks++) {
            const int k0 = ks * 8;
            unsigned q0v = __shfl_sync(0xffffffffu, pt[ks][0], ls);
            unsigned q1v = __shfl_sync(0xffffffffu, pt[ks][1], ls);
            unsigned q2v = __shfl_sync(0xffffffffu, pt[ks][2], ls);
            unsigned q3v = __shfl_sync(0xffffffffu, pt[ks][3], ls);
            unsigned u0v = __shfl_sync(0xffffffffu, pt[ks][0], ls2);
            unsigned u1v = __shfl_sync(0xffffffffu, pt[ks][1], ls2);
            unsigned u2v = __shfl_sync(0xffffffffu, pt[ks][2], ls2);
            unsigned u3v = __shfl_sync(0xffffffffu, pt[ks][3], ls2);
            unsigned a0 = odd ? q1v : q0v;
            unsigned a1 = odd ? q3v : q2v;
            unsigned a2 = odd ? u1v : u0v;
            unsigned a3 = odd ? u3v : u2v;
            unsigned vt2[4][4];
#pragma unroll
            for (int p = 0; p < 4; p++)
                ldsm4(vt2[p][0], vt2[p][1], vt2[p][2], vt2[p][3],
                      sbase + (vb_off[p] + k0) * 4);
#pragma unroll
            for (int nb = 0; nb < 8; nb++)
                mma_tf32(O[nb], a0, a1, a2, a3,
                         vt2[nb >> 1][(nb & 1) * 2],
                         vt2[nb >> 1][(nb & 1) * 2 + 1]);
        }

        if (t + 2 < nT) issue_kv(t + 2);
        CP_COMMIT();
    }

    // Normalize + write ctx (tf32-rounded for the proj GEMM)
    const float inv0 = 1.f / l0;
    const float inv1 = 1.f / l1;
    const int bb = bh >> 4;
    const int h = bh & 15;
    const int row0 = q0 + qw + r;
    const int row1 = row0 + 8;
#pragma unroll
    for (int nb = 0; nb < 8; nb++) {
        const int col = h * 64 + nb * 8 + 2 * c;
        float2 w0 = { __uint_as_float(f2tf(O[nb][0] * inv0)),
                      __uint_as_float(f2tf(O[nb][1] * inv0)) };
        float2 w1 = { __uint_as_float(f2tf(O[nb][2] * inv1)),
                      __uint_as_float(f2tf(O[nb][3] * inv1)) };
        *(float2*)&g_ctx[((size_t)(bb * N_ + row0)) * C_ + col] = w0;
        *(float2*)&g_ctx[((size_t)(bb * N_ + row1)) * C_ + col] = w1;
    }
}

// ---------------------------------------------------------------------------
extern "C" void kernel_launch(void* const* d_in, const int* in_sizes, int n_in,
                              void* d_out, int out_size)
{
    const float* x      = (const float*)d_in[0];
    const float* w_qkv  = (const float*)d_in[1];
    const float* w_proj = (const float*)d_in[2];
    const float* b_proj = (const float*)d_in[3];
    float* out = (float*)d_out;

    cudaFuncSetAttribute(mma_gemm<0>,
                         cudaFuncAttributeMaxDynamicSharedMemorySize, G_SMEM);
    cudaFuncSetAttribute(mma_gemm<1>,
                         cudaFuncAttributeMaxDynamicSharedMemorySize, G_SMEM);
    cudaFuncSetAttribute(mma_attn,
                         cudaFuncAttributeMaxDynamicSharedMemorySize, ATTN_SMEM);

    float* xr; float* wqT; float* wpT;
    cudaGetSymbolAddress((void**)&xr, g_xr);
    cudaGetSymbolAddress((void**)&wqT, g_wqkv);
    cudaGetSymbolAddress((void**)&wpT, g_wproj);

    // 0) pre-pass: round x; transpose+round weights
    {
        int n4x = MROWS * C_ / 4;
        round_tf32_kernel<<<n4x / 256, 256>>>((const float4*)x, (float4*)xr, n4x);
        dim3 tb(32, 8);
        transpose_round_kernel<<<dim3(3 * C_ / 32, C_ / 32), tb>>>(w_qkv, wqT, C_, 3 * C_);
        transpose_round_kernel<<<dim3(C_ / 32, C_ / 32), tb>>>(w_proj, wpT, C_, C_);
    }

    // 1) QKV projection: [8192,1024] @ w_qkv -> q/k/v (v transposed)
    mma_gemm<0><<<dim3(3 * C_ / 128, MROWS / 128), 256, G_SMEM>>>(
        xr, wqT, nullptr, nullptr, C_);

    // 2) Attention
    mma_attn<<<dim3(N_ / 128, BHn), 256, ATTN_SMEM>>>();

    // 3) Output projection + bias
    mma_gemm<1><<<dim3(C_ / 128, MROWS / 128), 256, G_SMEM>>>(
        nullptr, wpT, b_proj, out, C_);
}

// round 7
// speedup vs baseline: 9.0467x; 1.9180x over previous
#include <cuda_runtime.h>
#include <cuda_fp16.h>
#include <math_constants.h>
#include <cstdint>

// Problem constants
#define B_    4
#define N_    2048
#define C_    1024
#define H_    16
#define D_    64
#define BHn   (B_ * H_)          // 64
#define MROWS (B_ * N_)          // 8192

// Scratch (static device arrays; no runtime allocation)
__device__ __half g_qh[(size_t)BHn * N_ * D_];    // [bh][n][d], pre-scaled
__device__ __half g_kh[(size_t)BHn * N_ * D_];    // [bh][n][d]
__device__ __half g_vh[(size_t)BHn * N_ * D_];    // [bh][d][n]  (TRANSPOSED)
__device__ __half g_ctxh[(size_t)MROWS * C_];     // [b*n][c]
__device__ __half g_xh[(size_t)MROWS * C_];       // x, fp16
__device__ __half g_wqkvh[(size_t)3 * C_ * C_];   // w_qkv^T  [3072][1024]
__device__ __half g_wprojh[(size_t)C_ * C_];      // w_proj^T [1024][1024]

// ---------------------------------------------------------------------------
// Helpers
// ---------------------------------------------------------------------------
__device__ __forceinline__ void mma_f16(float* d,
    unsigned a0, unsigned a1, unsigned a2, unsigned a3,
    unsigned b0, unsigned b1)
{
    asm volatile(
        "mma.sync.aligned.m16n8k16.row.col.f32.f16.f16.f32 "
        "{%0,%1,%2,%3}, {%4,%5,%6,%7}, {%8,%9}, {%0,%1,%2,%3};"
        : "+f"(d[0]), "+f"(d[1]), "+f"(d[2]), "+f"(d[3])
        : "r"(a0), "r"(a1), "r"(a2), "r"(a3), "r"(b0), "r"(b1));
}

__device__ __forceinline__ unsigned smem_u32(const void* p) {
    return (unsigned)__cvta_generic_to_shared(p);
}
__device__ __forceinline__ void cpa16(unsigned s, const void* g) {
    asm volatile("cp.async.cg.shared.global [%0], [%1], 16;" :: "r"(s), "l"(g));
}
#define CP_COMMIT() asm volatile("cp.async.commit_group;")
#define CP_WAIT2()  asm volatile("cp.async.wait_group 2;")

__device__ __forceinline__ void ldsm4(unsigned& r0, unsigned& r1,
                                      unsigned& r2, unsigned& r3, unsigned addr)
{
    asm volatile(
        "ldmatrix.sync.aligned.m8n8.x4.shared.b16 {%0,%1,%2,%3}, [%4];"
        : "=r"(r0), "=r"(r1), "=r"(r2), "=r"(r3) : "r"(addr));
}

__device__ __forceinline__ unsigned sw64(unsigned off)  { return off ^ ((off >> 3) & 0x30); }
__device__ __forceinline__ unsigned sw128(unsigned off) { return off ^ ((off >> 3) & 0x70); }

__device__ __forceinline__ unsigned packh2(float lo, float hi) {
    __half2 h = __floats2half2_rn(lo, hi);
    return *(unsigned*)&h;
}

// ---------------------------------------------------------------------------
// Pre-pass kernels
// ---------------------------------------------------------------------------
__global__ void f2h_kernel(const float4* __restrict__ in,
                           __half2* __restrict__ out, int n4)
{
    int i = blockIdx.x * blockDim.x + threadIdx.x;
    if (i < n4) {
        float4 v = in[i];
        out[2 * i + 0] = __floats2half2_rn(v.x, v.y);
        out[2 * i + 1] = __floats2half2_rn(v.z, v.w);
    }
}

// in [K][Nn] fp32 -> outT [Nn][K] fp16
__global__ void transpose_h_kernel(const float* __restrict__ in,
                                   __half* __restrict__ outT, int K, int Nn)
{
    __shared__ float t[32][33];
    const int bx = blockIdx.x * 32;   // n
    const int by = blockIdx.y * 32;   // k
    const int x = threadIdx.x, y = threadIdx.y;
#pragma unroll
    for (int i = 0; i < 32; i += 8)
        t[y + i][x] = in[(size_t)(by + y + i) * Nn + bx + x];
    __syncthreads();
#pragma unroll
    for (int i = 0; i < 32; i += 8)
        outT[(size_t)(bx + y + i) * K + by + x] = __float2half_rn(t[x][y + i]);
}

// ---------------------------------------------------------------------------
// FP16 GEMM via mma.sync m16n8k16 + ldmatrix.
// D[m][n] = sum_k A[m][k] * Bt[n][k]. 128x128 CTA tile, k-chunk 32 halves.
// 256 threads, warp grid 2m x 4n, warp tile 64x32. SW64 swizzle on 64B rows.
// 4-stage cp.async ring, lookahead 3.
// MODE 0: scatter q/k/v (q scaled, v transposed). MODE 1: +bias -> fp32 Cout.
// ---------------------------------------------------------------------------
#define G_STAGE_BYTES (128 * 64 * 2)          // A 8KB + B 8KB
#define G_SMEM (4 * G_STAGE_BYTES)            // 65536

template <int MODE>
__global__ __launch_bounds__(256, 2) void hgemm(
    const __half* __restrict__ A, const __half* __restrict__ Bt,
    const float* __restrict__ bias, float* __restrict__ Cout, int K)
{
    extern __shared__ char hsm[];
    const unsigned sbase0 = smem_u32(hsm);

    const int tid  = threadIdx.x;
    const int lane = tid & 31;
    const int wid  = tid >> 5;
    const int wm = (wid & 1) * 64;
    const int wn = (wid >> 1) * 32;
    const int r = lane >> 2;
    const int c = lane & 3;
    const int mBase = blockIdx.y * 128;
    const int nBase = blockIdx.x * 128;

    const __half* Aptr = (MODE == 1) ? (const __half*)g_ctxh : A;

    // LDSM per-thread base byte offsets (within stage)
    const int mat = lane >> 3, mrr = lane & 7;
    unsigned a_base[4], b_base[2];
#pragma unroll
    for (int mi = 0; mi < 4; mi++) {
        const int row = wm + mi * 16 + mrr + (mat & 1) * 8;
        a_base[mi] = row * 64 + (mat >> 1) * 16;
    }
#pragma unroll
    for (int p = 0; p < 2; p++) {
        const int row = wn + p * 16 + ((mat >> 1) & 1) * 8 + mrr;
        b_base[p] = 8192 + row * 64 + (mat & 1) * 16;
    }

    auto issue_tile = [&](int t) {
        const unsigned base = sbase0 + (t & 3) * G_STAGE_BYTES;
        const int kt = t * 32;
#pragma unroll
        for (int i = 0; i < 2; i++) {          // A: 512 chunks of 16B
            const int idx = tid + i * 256;
            const int row = idx >> 2, kc = idx & 3;
            cpa16(base + sw64(row * 64 + kc * 16),
                  &Aptr[(size_t)(mBase + row) * K + kt + kc * 8]);
        }
#pragma unroll
        for (int i = 0; i < 2; i++) {          // B
            const int idx = tid + i * 256;
            const int row = idx >> 2, kc = idx & 3;
            cpa16(base + sw64(8192 + row * 64 + kc * 16),
                  &Bt[(size_t)(nBase + row) * K + kt + kc * 8]);
        }
    };

    float acc[4][4][4];
#pragma unroll
    for (int mi = 0; mi < 4; mi++)
#pragma unroll
        for (int ni = 0; ni < 4; ni++)
#pragma unroll
            for (int j = 0; j < 4; j++) acc[mi][ni][j] = 0.f;

    const int nT = K / 32;
    issue_tile(0); CP_COMMIT();
    issue_tile(1); CP_COMMIT();
    issue_tile(2); CP_COMMIT();

    for (int t = 0; t < nT; t++) {
        CP_WAIT2();
        __syncthreads();
        const unsigned sb = sbase0 + (t & 3) * G_STAGE_BYTES;

#pragma unroll
        for (int ks = 0; ks < 2; ks++) {
            unsigned a[4][4], bt2[2][4];
#pragma unroll
            for (int mi = 0; mi < 4; mi++)
                ldsm4(a[mi][0], a[mi][1], a[mi][2], a[mi][3],
                      sb + sw64(a_base[mi] + ks * 32));
#pragma unroll
            for (int p = 0; p < 2; p++)
                ldsm4(bt2[p][0], bt2[p][1], bt2[p][2], bt2[p][3],
                      sb + sw64(b_base[p] + ks * 32));
#pragma unroll
            for (int mi = 0; mi < 4; mi++)
#pragma unroll
                for (int ni = 0; ni < 4; ni++)
                    mma_f16(acc[mi][ni], a[mi][0], a[mi][1], a[mi][2], a[mi][3],
                            bt2[ni >> 1][(ni & 1) * 2],
                            bt2[ni >> 1][(ni & 1) * 2 + 1]);
        }

        if (t + 3 < nT) issue_tile(t + 3);
        CP_COMMIT();
    }

    // Epilogue
#pragma unroll
    for (int mi = 0; mi < 4; mi++) {
        const int row0 = mBase + wm + mi * 16 + r;
#pragma unroll
        for (int ni = 0; ni < 4; ni++) {
            const int col = nBase + wn + ni * 8 + 2 * c;
#pragma unroll
            for (int hh = 0; hh < 2; hh++) {
                const int m = row0 + hh * 8;
                float v0 = acc[mi][ni][2 * hh + 0];
                float v1 = acc[mi][ni][2 * hh + 1];
                if (MODE == 0) {
                    const int which = col >> 10;
                    const int cc = col & 1023;
                    const int h = cc >> 6;
                    const int d = cc & 63;
                    const int bb = m >> 11;
                    const int nn = m & 2047;
                    if (which == 0) {
                        __half2 w = __floats2half2_rn(v0 * 0.125f, v1 * 0.125f);
                        *(__half2*)&g_qh[(((size_t)(bb * H_ + h)) * N_ + nn) * D_ + d] = w;
                    } else if (which == 1) {
                        __half2 w = __floats2half2_rn(v0, v1);
                        *(__half2*)&g_kh[(((size_t)(bb * H_ + h)) * N_ + nn) * D_ + d] = w;
                    } else {
                        const size_t vb = ((size_t)(bb * H_ + h)) * D_;
                        g_vh[(vb + d) * N_ + nn]     = __float2half_rn(v0);
                        g_vh[(vb + d + 1) * N_ + nn] = __float2half_rn(v1);
                    }
                } else {
                    float2 w = { v0 + bias[col], v1 + bias[col + 1] };
                    *(float2*)&Cout[(size_t)m * C_ + col] = w;
                }
            }
        }
    }
}

// ---------------------------------------------------------------------------
// FP16 flash attention. CTA: 128 q rows, 8 warps x 16 q rows; k-tile 64 keys.
// K tile [64 keys][64 d] and V^T tile [64 d][64 keys], 128B rows, SW128.
// Q frags in registers; P A-frags are packed accumulator pairs (no shuffles).
// 4-stage cp.async ring, lookahead 3.
// ---------------------------------------------------------------------------
#define A_STAGE_BYTES (64 * 128 * 2)           // K 8KB + V 8KB
#define ATTN_SMEM (4 * A_STAGE_BYTES)          // 65536

__global__ __launch_bounds__(256, 2) void hattn()
{
    extern __shared__ char asmm[];
    const unsigned sbase0 = smem_u32(asmm);

    const int bh = blockIdx.y;
    const int q0 = blockIdx.x * 128;
    const int tid = threadIdx.x;
    const int lane = tid & 31;
    const int wid = tid >> 5;
    const int r = lane >> 2;
    const int c = lane & 3;
    const int qw = wid * 16;

    const __half* Kg = g_kh + (size_t)bh * N_ * D_;
    const __half* Vt = g_vh + (size_t)bh * D_ * N_;   // [d][n]

    // LDSM B-pattern base offsets (4 blocks of 16 rows)
    const int mat = lane >> 3, mrr = lane & 7;
    unsigned kb_base[4], vb_base[4];
#pragma unroll
    for (int p = 0; p < 4; p++) {
        const int row = p * 16 + ((mat >> 1) & 1) * 8 + mrr;
        kb_base[p] = row * 128 + (mat & 1) * 16;
        vb_base[p] = 8192 + row * 128 + (mat & 1) * 16;
    }

    auto issue_kv = [&](int t) {
        const unsigned base = sbase0 + (t & 3) * A_STAGE_BYTES;
        const int kt = t * 64;
#pragma unroll
        for (int i = 0; i < 4; i++) {
            const int idx = tid + i * 256;
            if (idx < 512) {                   // K tile: [key][d]
                const int row = idx >> 3, kc = idx & 7;
                cpa16(base + sw128(row * 128 + kc * 16),
                      &Kg[(size_t)(kt + row) * D_ + kc * 8]);
            } else {                           // V^T tile: [d][key]
                const int j = idx - 512;
                const int row = j >> 3, kc = j & 7;
                cpa16(base + sw128(8192 + row * 128 + kc * 16),
                      &Vt[(size_t)row * N_ + kt + kc * 8]);
            }
        }
    };

    // Q fragments -> registers (fp16, pre-scaled)
    unsigned qa[4][4];
    {
        const __half* Qr0 = g_qh + (size_t)bh * N_ * D_ + (size_t)(q0 + qw + r) * D_;
        const __half* Qr1 = Qr0 + 8 * D_;
#pragma unroll
        for (int ks = 0; ks < 4; ks++) {
            const int k0 = ks * 16 + 2 * c;
            qa[ks][0] = *(const unsigned*)&Qr0[k0];
            qa[ks][1] = *(const unsigned*)&Qr1[k0];
            qa[ks][2] = *(const unsigned*)&Qr0[k0 + 8];
            qa[ks][3] = *(const unsigned*)&Qr1[k0 + 8];
        }
    }

    float m0 = -CUDART_INF_F, m1 = -CUDART_INF_F, l0 = 0.f, l1 = 0.f;
    float O[8][4];
#pragma unroll
    for (int nb = 0; nb < 8; nb++)
#pragma unroll
        for (int j = 0; j < 4; j++) O[nb][j] = 0.f;

    const int nT = N_ / 64;
    issue_kv(0); CP_COMMIT();
    issue_kv(1); CP_COMMIT();
    issue_kv(2); CP_COMMIT();

    for (int t = 0; t < nT; t++) {
        CP_WAIT2();
        __syncthreads();
        const unsigned sb = sbase0 + (t & 3) * A_STAGE_BYTES;

        // S = Q @ K^T
        float s[8][4];
#pragma unroll
        for (int nb = 0; nb < 8; nb++)
#pragma unroll
            for (int j = 0; j < 4; j++) s[nb][j] = 0.f;

#pragma unroll
        for (int ks = 0; ks < 4; ks++) {
            unsigned bt2[4][4];
#pragma unroll
            for (int p = 0; p < 4; p++)
                ldsm4(bt2[p][0], bt2[p][1], bt2[p][2], bt2[p][3],
                      sb + sw128(kb_base[p] + ks * 32));
#pragma unroll
            for (int nb = 0; nb < 8; nb++)
                mma_f16(s[nb], qa[ks][0], qa[ks][1], qa[ks][2], qa[ks][3],
                        bt2[nb >> 1][(nb & 1) * 2],
                        bt2[nb >> 1][(nb & 1) * 2 + 1]);
        }

        // Online softmax (rows r, r+8; quad reduction)
        float mx0 = -CUDART_INF_F, mx1 = -CUDART_INF_F;
#pragma unroll
        for (int nb = 0; nb < 8; nb++) {
            mx0 = fmaxf(mx0, fmaxf(s[nb][0], s[nb][1]));
            mx1 = fmaxf(mx1, fmaxf(s[nb][2], s[nb][3]));
        }
        mx0 = fmaxf(mx0, __shfl_xor_sync(0xffffffffu, mx0, 1));
        mx0 = fmaxf(mx0, __shfl_xor_sync(0xffffffffu, mx0, 2));
        mx1 = fmaxf(mx1, __shfl_xor_sync(0xffffffffu, mx1, 1));
        mx1 = fmaxf(mx1, __shfl_xor_sync(0xffffffffu, mx1, 2));
        const float mn0 = fmaxf(m0, mx0);
        const float mn1 = fmaxf(m1, mx1);
        const float al0 = __expf(m0 - mn0);
        const float al1 = __expf(m1 - mn1);
        m0 = mn0; m1 = mn1;
        float rs0 = 0.f, rs1 = 0.f;
#pragma unroll
        for (int nb = 0; nb < 8; nb++) {
            s[nb][0] = __expf(s[nb][0] - mn0);
            s[nb][1] = __expf(s[nb][1] - mn0);
            rs0 += s[nb][0] + s[nb][1];
            s[nb][2] = __expf(s[nb][2] - mn1);
            s[nb][3] = __expf(s[nb][3] - mn1);
            rs1 += s[nb][2] + s[nb][3];
        }
        rs0 += __shfl_xor_sync(0xffffffffu, rs0, 1);
        rs0 += __shfl_xor_sync(0xffffffffu, rs0, 2);
        rs1 += __shfl_xor_sync(0xffffffffu, rs1, 1);
        rs1 += __shfl_xor_sync(0xffffffffu, rs1, 2);
        l0 = l0 * al0 + rs0;
        l1 = l1 * al1 + rs1;
#pragma unroll
        for (int nb = 0; nb < 8; nb++) {
            O[nb][0] *= al0; O[nb][1] *= al0;
            O[nb][2] *= al1; O[nb][3] *= al1;
        }

        // O += P @ V : P A-frags = packed accumulator pairs (no shuffles)
#pragma unroll
        for (int ks = 0; ks < 4; ks++) {
            const unsigned a0 = packh2(s[2 * ks][0], s[2 * ks][1]);
            const unsigned a1 = packh2(s[2 * ks][2], s[2 * ks][3]);
            const unsigned a2 = packh2(s[2 * ks + 1][0], s[2 * ks + 1][1]);
            const unsigned a3 = packh2(s[2 * ks + 1][2], s[2 * ks + 1][3]);
            unsigned vt2[4][4];
#pragma unroll
            for (int p = 0; p < 4; p++)
                ldsm4(vt2[p][0], vt2[p][1], vt2[p][2], vt2[p][3],
                      sb + sw128(vb_base[p] + ks * 32));
#pragma unroll
            for (int nb = 0; nb < 8; nb++)
                mma_f16(O[nb], a0, a1, a2, a3,
                        vt2[nb >> 1][(nb & 1) * 2],
                        vt2[nb >> 1][(nb & 1) * 2 + 1]);
        }

        if (t + 3 < nT) issue_kv(t + 3);
        CP_COMMIT();
    }

    // Normalize + write ctx fp16 [b*n][h*64+d]
    const float inv0 = 1.f / l0;
    const float inv1 = 1.f / l1;
    const int bb = bh >> 4;
    const int h = bh & 15;
    const int row0 = q0 + qw + r;
    const int row1 = row0 + 8;
#pragma unroll
    for (int nb = 0; nb < 8; nb++) {
        const int col = h * 64 + nb * 8 + 2 * c;
        __half2 w0 = __floats2half2_rn(O[nb][0] * inv0, O[nb][1] * inv0);
        __half2 w1 = __floats2half2_rn(O[nb][2] * inv1, O[nb][3] * inv1);
        *(__half2*)&g_ctxh[((size_t)(bb * N_ + row0)) * C_ + col] = w0;
        *(__half2*)&g_ctxh[((size_t)(bb * N_ + row1)) * C_ + col] = w1;
    }
}

// ---------------------------------------------------------------------------
extern "C" void kernel_launch(void* const* d_in, const int* in_sizes, int n_in,
                              void* d_out, int out_size)
{
    const float* x      = (const float*)d_in[0];
    const float* w_qkv  = (const float*)d_in[1];
    const float* w_proj = (const float*)d_in[2];
    const float* b_proj = (const float*)d_in[3];
    float* out = (float*)d_out;

    cudaFuncSetAttribute(hgemm<0>,
                         cudaFuncAttributeMaxDynamicSharedMemorySize, G_SMEM);
    cudaFuncSetAttribute(hgemm<1>,
                         cudaFuncAttributeMaxDynamicSharedMemorySize, G_SMEM);
    cudaFuncSetAttribute(hattn,
                         cudaFuncAttributeMaxDynamicSharedMemorySize, ATTN_SMEM);

    __half* xh; __half* wqT; __half* wpT;
    cudaGetSymbolAddress((void**)&xh, g_xh);
    cudaGetSymbolAddress((void**)&wqT, g_wqkvh);
    cudaGetSymbolAddress((void**)&wpT, g_wprojh);

    // 0) pre-pass: x -> fp16; weights -> transposed fp16
    {
        int n4x = MROWS * C_ / 4;
        f2h_kernel<<<n4x / 256, 256>>>((const float4*)x, (__half2*)xh, n4x);
        dim3 tb(32, 8);
        transpose_h_kernel<<<dim3(3 * C_ / 32, C_ / 32), tb>>>(w_qkv, wqT, C_, 3 * C_);
        transpose_h_kernel<<<dim3(C_ / 32, C_ / 32), tb>>>(w_proj, wpT, C_, C_);
    }

    // 1) QKV projection: [8192,1024] @ w_qkv -> q/k/v (v transposed)
    hgemm<0><<<dim3(3 * C_ / 128, MROWS / 128), 256, G_SMEM>>>(
        xh, wqT, nullptr, nullptr, C_);

    // 2) Attention
    hattn<<<dim3(N_ / 128, BHn), 256, ATTN_SMEM>>>();

    // 3) Output projection + bias (fp32 out)
    hgemm<1><<<dim3(C_ / 128, MROWS / 128), 256, G_SMEM>>>(
        nullptr, wpT, b_proj, out, C_);
}